// round 3
// baseline (speedup 1.0000x reference)
#include <cuda_runtime.h>

// RAPiD detection-head decode, vectorized smem-staged coalesced stores.
// raw:     (64, 18, 128, 128) fp32, channel c = a*6 + ch
// anchors: (3, 2) fp32
// img_h, img_w: int32 scalars (device)
// out:     (64, 3*128*128, 6) fp32, layout [b][a][h][w][ch]

#define NB 64
#define NA 3
#define NH 128
#define NW 128
#define PLANE (NH * NW)           // 16384
#define ANGLE_RANGE 360.0f
#define TPB 256
#define LANE_F4 7                 // float4 slots per lane in smem (6 data + 1 pad)

__device__ __forceinline__ float sigmoidf_fast(float x) {
    return 1.0f / (1.0f + __expf(-x));
}

__global__ void __launch_bounds__(TPB) rapid_decode_kernel(
    const float* __restrict__ raw,
    const float* __restrict__ anchors,
    const int*   __restrict__ img_h_p,
    const int*   __restrict__ img_w_p,
    float*       __restrict__ out)
{
    __shared__ float4 sh[TPB * LANE_F4];   // 28 KB

    const int tid = threadIdx.x;
    const int bid = blockIdx.x;

    // Each (b,a) slice = 32*128 = 4096 threads = 16 blocks -> a,b uniform per block.
    const int a = (bid >> 4) % NA;
    const int b = bid / (16 * NA);
    const int slice_t = ((bid & 15) << 8) + tid;   // 0..4095 within (b,a) slice
    const int w4 = slice_t & 31;                    // group of 4 along w
    const int h  = slice_t >> 5;                    // 0..127

    const float sx = (float)img_w_p[0] / (float)NW;
    const float sy = (float)img_h_p[0] / (float)NH;
    const float aw = anchors[a * 2 + 0];
    const float ah = anchors[a * 2 + 1];

    const int w0 = w4 * 4;
    const float* base = raw + (size_t)((b * 18 + a * 6) * PLANE + h * NW + w0);

    // 6 channel planes, 64KB apart; each LDG.128 fully coalesced.
    float4 r0 = *(const float4*)(base + 0 * PLANE);
    float4 r1 = *(const float4*)(base + 1 * PLANE);
    float4 r2 = *(const float4*)(base + 2 * PLANE);
    float4 r3 = *(const float4*)(base + 3 * PLANE);
    float4 r4 = *(const float4*)(base + 4 * PLANE);
    float4 r5 = *(const float4*)(base + 5 * PLANE);

    float v0[4] = {r0.x, r0.y, r0.z, r0.w};
    float v1[4] = {r1.x, r1.y, r1.z, r1.w};
    float v2[4] = {r2.x, r2.y, r2.z, r2.w};
    float v3[4] = {r3.x, r3.y, r3.z, r3.w};
    float v4[4] = {r4.x, r4.y, r4.z, r4.w};
    float v5[4] = {r5.x, r5.y, r5.z, r5.w};

    // Compute 24 outputs directly in output (pixel-interleaved) order.
    float o[24];
    #pragma unroll
    for (int i = 0; i < 4; i++) {
        o[i * 6 + 0] = (sigmoidf_fast(v0[i]) + (float)(w0 + i)) * sx;
        o[i * 6 + 1] = (sigmoidf_fast(v1[i]) + (float)h)        * sy;
        o[i * 6 + 2] = __expf(v2[i]) * aw;
        o[i * 6 + 3] = __expf(v3[i]) * ah;
        o[i * 6 + 4] = sigmoidf_fast(v4[i]) * ANGLE_RANGE - ANGLE_RANGE * 0.5f;
        o[i * 6 + 5] = sigmoidf_fast(v5[i]);
    }

    const int lane = tid & 31;
    const int warp = tid >> 5;
    float4* wsh = sh + warp * 32 * LANE_F4;

    // Stage 6 float4s (output order) with stride-7 padding:
    // within each 8-lane STS.128 phase, 7*lane mod 8 is a permutation -> conflict-free.
    #pragma unroll
    for (int j = 0; j < 6; j++) {
        wsh[lane * LANE_F4 + j] =
            make_float4(o[j * 4 + 0], o[j * 4 + 1], o[j * 4 + 2], o[j * 4 + 3]);
    }

    __syncwarp();

    // Copy-out: warp's 192 float4s form one contiguous 3072B output region.
    const size_t warp_pix0 = (size_t)(bid * TPB + warp * 32) * 4;
    float4* op = (float4*)(out + warp_pix0 * 6);

    #pragma unroll
    for (int k = 0; k < 6; k++) {
        int g = lane + 32 * k;            // output float4 index within warp tile
        int row = g / 6;                  // producing lane
        int col = g - row * 6;
        op[g] = wsh[row * LANE_F4 + col]; // LDS.128 -> STG.128 fully coalesced
    }
}

extern "C" void kernel_launch(void* const* d_in, const int* in_sizes, int n_in,
                              void* d_out, int out_size)
{
    const float* raw     = (const float*)d_in[0];
    const float* anchors = (const float*)d_in[1];
    const int*   img_h   = (const int*)d_in[2];
    const int*   img_w   = (const int*)d_in[3];
    float* out = (float*)d_out;

    const int total_threads = NB * NA * NH * (NW / 4); // 786432
    const int grid = total_threads / TPB;              // 3072
    rapid_decode_kernel<<<grid, TPB>>>(raw, anchors, img_h, img_w, out);
}

// round 5
// speedup vs baseline: 1.0011x; 1.0011x over previous
#include <cuda_runtime.h>

// RAPiD detection-head decode, vectorized smem-staged coalesced stores.
// raw:     (64, 18, 128, 128) fp32, channel c = a*6 + ch
// anchors: (3, 2) fp32
// img_h, img_w: int32 scalars (device)
// out:     (64, 3*128*128, 6) fp32, layout [b][a][h][w][ch]

#define NB 64
#define NA 3
#define NH 128
#define NW 128
#define PLANE (NH * NW)           // 16384
#define ANGLE_RANGE 360.0f
#define TPB 256
#define LANE_F4 7                 // float4 slots per lane in smem (6 data + 1 pad)

__device__ __forceinline__ float sigmoidf_fast(float x) {
    return 1.0f / (1.0f + __expf(-x));
}

__global__ void __launch_bounds__(TPB) rapid_decode_kernel(
    const float* __restrict__ raw,
    const float* __restrict__ anchors,
    const int*   __restrict__ img_h_p,
    const int*   __restrict__ img_w_p,
    float*       __restrict__ out)
{
    __shared__ float4 sh[TPB * LANE_F4];   // 28 KB

    const int tid = threadIdx.x;
    const int bid = blockIdx.x;

    // Each (b,a) slice = 32*128 = 4096 threads = 16 blocks -> a,b uniform per block.
    const int a = (bid >> 4) % NA;
    const int b = bid / (16 * NA);
    const int slice_t = ((bid & 15) << 8) + tid;   // 0..4095 within (b,a) slice
    const int w4 = slice_t & 31;                    // group of 4 along w
    const int h  = slice_t >> 5;                    // 0..127

    const float sx = (float)img_w_p[0] / (float)NW;
    const float sy = (float)img_h_p[0] / (float)NH;
    const float aw = anchors[a * 2 + 0];
    const float ah = anchors[a * 2 + 1];

    const int w0 = w4 * 4;
    const float* base = raw + (size_t)((b * 18 + a * 6) * PLANE + h * NW + w0);

    // 6 channel planes, 64KB apart; each LDG.128 fully coalesced.
    float4 r0 = *(const float4*)(base + 0 * PLANE);
    float4 r1 = *(const float4*)(base + 1 * PLANE);
    float4 r2 = *(const float4*)(base + 2 * PLANE);
    float4 r3 = *(const float4*)(base + 3 * PLANE);
    float4 r4 = *(const float4*)(base + 4 * PLANE);
    float4 r5 = *(const float4*)(base + 5 * PLANE);

    float v0[4] = {r0.x, r0.y, r0.z, r0.w};
    float v1[4] = {r1.x, r1.y, r1.z, r1.w};
    float v2[4] = {r2.x, r2.y, r2.z, r2.w};
    float v3[4] = {r3.x, r3.y, r3.z, r3.w};
    float v4[4] = {r4.x, r4.y, r4.z, r4.w};
    float v5[4] = {r5.x, r5.y, r5.z, r5.w};

    // Compute 24 outputs directly in output (pixel-interleaved) order.
    float o[24];
    #pragma unroll
    for (int i = 0; i < 4; i++) {
        o[i * 6 + 0] = (sigmoidf_fast(v0[i]) + (float)(w0 + i)) * sx;
        o[i * 6 + 1] = (sigmoidf_fast(v1[i]) + (float)h)        * sy;
        o[i * 6 + 2] = __expf(v2[i]) * aw;
        o[i * 6 + 3] = __expf(v3[i]) * ah;
        o[i * 6 + 4] = sigmoidf_fast(v4[i]) * ANGLE_RANGE - ANGLE_RANGE * 0.5f;
        o[i * 6 + 5] = sigmoidf_fast(v5[i]);
    }

    const int lane = tid & 31;
    const int warp = tid >> 5;
    float4* wsh = sh + warp * 32 * LANE_F4;

    // Stage 6 float4s (output order) with stride-7 padding:
    // within each 8-lane STS.128 phase, 7*lane mod 8 is a permutation -> conflict-free.
    #pragma unroll
    for (int j = 0; j < 6; j++) {
        wsh[lane * LANE_F4 + j] =
            make_float4(o[j * 4 + 0], o[j * 4 + 1], o[j * 4 + 2], o[j * 4 + 3]);
    }

    __syncwarp();

    // Copy-out: warp's 192 float4s form one contiguous 3072B output region.
    const size_t warp_pix0 = (size_t)(bid * TPB + warp * 32) * 4;
    float4* op = (float4*)(out + warp_pix0 * 6);

    #pragma unroll
    for (int k = 0; k < 6; k++) {
        int g = lane + 32 * k;            // output float4 index within warp tile
        int row = g / 6;                  // producing lane
        int col = g - row * 6;
        op[g] = wsh[row * LANE_F4 + col]; // LDS.128 -> STG.128 fully coalesced
    }
}

extern "C" void kernel_launch(void* const* d_in, const int* in_sizes, int n_in,
                              void* d_out, int out_size)
{
    const float* raw     = (const float*)d_in[0];
    const float* anchors = (const float*)d_in[1];
    const int*   img_h   = (const int*)d_in[2];
    const int*   img_w   = (const int*)d_in[3];
    float* out = (float*)d_out;

    const int total_threads = NB * NA * NH * (NW / 4); // 786432
    const int grid = total_threads / TPB;              // 3072
    rapid_decode_kernel<<<grid, TPB>>>(raw, anchors, img_h, img_w, out);
}